// round 6
// baseline (speedup 1.0000x reference)
#include <cuda_runtime.h>

#define B_  4
#define L_  1024
#define D_  512
#define H_  8
#define DK_ 64

// ---------------- scratch (no allocations allowed) ----------------
__device__ float g_Q [B_*L_*D_];
__device__ float g_K [B_*L_*D_];
__device__ float g_V [B_*L_*D_];
__device__ float g_QP[B_*L_*D_];
__device__ float g_KP[B_*L_*D_];
__device__ float g_AV[B_*L_*D_];
__device__ float g_g [B_*L_];

// =================================================================
// Generic SGEMM: C[M,N] = A[M,K] @ W[K,N] + bias[N]   (all row-major)
// 64x64 tile, BK=32, 256 threads, 4x4 micro-tile.
// =================================================================
__global__ __launch_bounds__(256) void sgemm_bias_kernel(
    const float* __restrict__ A, const float* __restrict__ W,
    const float* __restrict__ bias, float* __restrict__ C,
    int M, int N, int K)
{
    __shared__ float As[64][33];
    __shared__ float Ws[32][64];
    const int tid = threadIdx.x;
    const int tx = tid & 15, ty = tid >> 4;
    const int m0 = blockIdx.y * 64, n0 = blockIdx.x * 64;

    float acc[4][4] = {};

    for (int k0 = 0; k0 < K; k0 += 32) {
        #pragma unroll
        for (int l = 0; l < 2; l++) {
            int idx = tid + l * 256;            // 512 float4 loads: 64x32 A tile
            int r = idx >> 3, c = (idx & 7) << 2;
            float4 v = *(const float4*)(A + (size_t)(m0 + r) * K + k0 + c);
            As[r][c+0] = v.x; As[r][c+1] = v.y; As[r][c+2] = v.z; As[r][c+3] = v.w;
        }
        #pragma unroll
        for (int l = 0; l < 2; l++) {
            int idx = tid + l * 256;            // 512 float4 loads: 32x64 W tile
            int r = idx >> 4, c = (idx & 15) << 2;
            *(float4*)&Ws[r][c] = *(const float4*)(W + (size_t)(k0 + r) * N + n0 + c);
        }
        __syncthreads();

        #pragma unroll 8
        for (int kk = 0; kk < 32; kk++) {
            float a_[4];
            #pragma unroll
            for (int i = 0; i < 4; i++) a_[i] = As[ty * 4 + i][kk];
            float4 b4 = *(float4*)&Ws[kk][tx * 4];
            float b_[4] = {b4.x, b4.y, b4.z, b4.w};
            #pragma unroll
            for (int i = 0; i < 4; i++)
                #pragma unroll
                for (int j = 0; j < 4; j++)
                    acc[i][j] += a_[i] * b_[j];
        }
        __syncthreads();
    }

    float4 bv = *(const float4*)(bias + n0 + tx * 4);
    #pragma unroll
    for (int i = 0; i < 4; i++) {
        int row = m0 + ty * 4 + i;
        float4 o = make_float4(acc[i][0] + bv.x, acc[i][1] + bv.y,
                               acc[i][2] + bv.z, acc[i][3] + bv.w);
        *(float4*)(C + (size_t)row * N + n0 + tx * 4) = o;
    }
}

// =================================================================
// m kernel: per batch  m = sigmoid( (QP @ KP^T) / sqrt(512) )
// NT GEMM, 64x64 tile, BK=32, fused sigmoid epilogue -> d_out m region
// =================================================================
__global__ __launch_bounds__(256) void m_kernel(
    const float* __restrict__ QP, const float* __restrict__ KP,
    float* __restrict__ Mout)
{
    const int bz = blockIdx.z;
    const float* A  = QP + (size_t)bz * L_ * D_;
    const float* Bp = KP + (size_t)bz * L_ * D_;
    float* C = Mout + (size_t)bz * L_ * L_;

    __shared__ float As[64][33];
    __shared__ float Bs[64][33];
    const int tid = threadIdx.x;
    const int tx = tid & 15, ty = tid >> 4;
    const int m0 = blockIdx.y * 64, n0 = blockIdx.x * 64;

    float acc[4][4] = {};

    for (int k0 = 0; k0 < D_; k0 += 32) {
        #pragma unroll
        for (int l = 0; l < 2; l++) {
            int idx = tid + l * 256;
            int r = idx >> 3, c = (idx & 7) << 2;
            float4 v = *(const float4*)(A + (size_t)(m0 + r) * D_ + k0 + c);
            As[r][c+0] = v.x; As[r][c+1] = v.y; As[r][c+2] = v.z; As[r][c+3] = v.w;
            float4 w = *(const float4*)(Bp + (size_t)(n0 + r) * D_ + k0 + c);
            Bs[r][c+0] = w.x; Bs[r][c+1] = w.y; Bs[r][c+2] = w.z; Bs[r][c+3] = w.w;
        }
        __syncthreads();

        #pragma unroll 8
        for (int kk = 0; kk < 32; kk++) {
            float a_[4], b_[4];
            #pragma unroll
            for (int i = 0; i < 4; i++) a_[i] = As[ty * 4 + i][kk];
            #pragma unroll
            for (int j = 0; j < 4; j++) b_[j] = Bs[tx * 4 + j][kk];
            #pragma unroll
            for (int i = 0; i < 4; i++)
                #pragma unroll
                for (int j = 0; j < 4; j++)
                    acc[i][j] += a_[i] * b_[j];
        }
        __syncthreads();
    }

    const float sc = 0.04419417382415922f;   // 1/sqrt(512)
    #pragma unroll
    for (int i = 0; i < 4; i++) {
        float4 o;
        o.x = 1.0f / (1.0f + __expf(-acc[i][0] * sc));
        o.y = 1.0f / (1.0f + __expf(-acc[i][1] * sc));
        o.z = 1.0f / (1.0f + __expf(-acc[i][2] * sc));
        o.w = 1.0f / (1.0f + __expf(-acc[i][3] * sc));
        *(float4*)(C + (size_t)(m0 + ty * 4 + i) * L_ + n0 + tx * 4) = o;
    }
}

// =================================================================
// gate kernel: g = sigmoid(query @ gate_w + gate_b), one warp per row
// =================================================================
__global__ __launch_bounds__(256) void gate_kernel(
    const float* __restrict__ query, const float* __restrict__ gw,
    const float* __restrict__ gb, float* __restrict__ g)
{
    const int row  = blockIdx.x * 8 + (threadIdx.x >> 5);
    const int lane = threadIdx.x & 31;
    const float* q = query + (size_t)row * D_;
    float s = 0.f;
    #pragma unroll
    for (int k = lane; k < D_; k += 32) s += q[k] * gw[k];
    #pragma unroll
    for (int o = 16; o; o >>= 1) s += __shfl_xor_sync(0xffffffffu, s, o);
    if (lane == 0) g[row] = 1.0f / (1.0f + __expf(-(s + gb[0])));
}

// =================================================================
// Fused attention kernel: one block = (b, h, 32 query rows).
// Keeps full 32x1024 score block in smem; two softmaxes + calibration
// fused; P@V with second-softmax normalization folded into epilogue.
// =================================================================
#define S_STRIDE 1028
#define QT_OFF   (32 * 1028)
#define KT_OFF   (QT_OFF + 64 * 36)
#define SMEM_FLOATS (KT_OFF + 8704)
#define ATTN_SMEM_BYTES (SMEM_FLOATS * 4)

__global__ __launch_bounds__(256) void attn_kernel(
    const float* __restrict__ Q, const float* __restrict__ Kg,
    const float* __restrict__ Vg, const float* __restrict__ Mg,
    const float* __restrict__ gate, float* __restrict__ AV)
{
    extern __shared__ float sm[];
    float* S  = sm;              // [32][1028] scores / probs
    float* QT = sm + QT_OFF;     // [64][36]   Q transposed [d][q]
    float* KT = sm + KT_OFF;     // [64][132]  K transposed [d][k]  (also V tile [128][68])
    __shared__ float rowInv[32];

    const int tid = threadIdx.x;
    const int b = blockIdx.z, h = blockIdx.y, q0 = blockIdx.x * 32;

    const float* Qb = Q  + ((size_t)(b * L_ + q0)) * D_ + h * DK_;
    const float* Kb = Kg + (size_t)b * L_ * D_ + h * DK_;
    const float* Vb = Vg + (size_t)b * L_ * D_ + h * DK_;
    const float* Mb = Mg + (size_t)b * L_ * L_ + (size_t)q0 * L_;

    // ---- load Q tile transposed: QT[d][q] ----
    #pragma unroll
    for (int l = 0; l < 2; l++) {
        int idx = tid + l * 256;                 // 512 float4: 32 rows x 64
        int r = idx >> 4, c = (idx & 15) << 2;
        float4 v = *(const float4*)(Qb + (size_t)r * D_ + c);
        QT[(c+0)*36 + r] = v.x; QT[(c+1)*36 + r] = v.y;
        QT[(c+2)*36 + r] = v.z; QT[(c+3)*36 + r] = v.w;
    }

    // ---- phase 1: S = (Q K^T) * 1/sqrt(64) ----
    {
        const int tx = tid & 31, ty = tid >> 5;  // (32,8): 4q x 4k micro
        for (int k0 = 0; k0 < L_; k0 += 128) {
            #pragma unroll
            for (int l = 0; l < 8; l++) {
                int idx = tid + l * 256;         // 2048 float4: 128 rows x 64
                int r = idx >> 4, c = (idx & 15) << 2;
                float4 v = *(const float4*)(Kb + (size_t)(k0 + r) * D_ + c);
                KT[(c+0)*132 + r] = v.x; KT[(c+1)*132 + r] = v.y;
                KT[(c+2)*132 + r] = v.z; KT[(c+3)*132 + r] = v.w;
            }
            __syncthreads();

            float acc[4][4] = {};
            #pragma unroll 8
            for (int d = 0; d < 64; d++) {
                float4 a4 = *(float4*)(QT + d * 36  + ty * 4);
                float4 b4 = *(float4*)(KT + d * 132 + tx * 4);
                float a_[4] = {a4.x, a4.y, a4.z, a4.w};
                float b_[4] = {b4.x, b4.y, b4.z, b4.w};
                #pragma unroll
                for (int i = 0; i < 4; i++)
                    #pragma unroll
                    for (int j = 0; j < 4; j++)
                        acc[i][j] += a_[i] * b_[j];
            }
            #pragma unroll
            for (int i = 0; i < 4; i++)
                #pragma unroll
                for (int j = 0; j < 4; j++)
                    S[(ty*4 + i) * S_STRIDE + k0 + tx*4 + j] = acc[i][j] * 0.125f;
            __syncthreads();
        }
    }

    // ---- phase 2: softmax -> calibrate with m,g -> second softmax ----
    {
        const int warp = tid >> 5, lane = tid & 31;
        #pragma unroll
        for (int rr = 0; rr < 4; rr++) {
            const int r = warp * 4 + rr;
            float* Srow = S + r * S_STRIDE;

            float mx = -1e30f;
            for (int k = lane; k < L_; k += 32) mx = fmaxf(mx, Srow[k]);
            #pragma unroll
            for (int o = 16; o; o >>= 1) mx = fmaxf(mx, __shfl_xor_sync(0xffffffffu, mx, o));

            float sum = 0.f;
            for (int k = lane; k < L_; k += 32) {
                float e = __expf(Srow[k] - mx); Srow[k] = e; sum += e;
            }
            #pragma unroll
            for (int o = 16; o; o >>= 1) sum += __shfl_xor_sync(0xffffffffu, sum, o);
            const float inv = 1.0f / sum;

            const float gq = gate[b * L_ + q0 + r];
            const float* mrow = Mb + (size_t)r * L_;
            float cmax = -1e30f;
            for (int k = lane; k < L_; k += 32) {
                float w = gq + (1.0f - gq) * __expf(1.0f - mrow[k]);
                float c = Srow[k] * inv * w;          // g*p + (1-g)*p*e^{1-m}
                Srow[k] = c;
                cmax = fmaxf(cmax, c);
            }
            #pragma unroll
            for (int o = 16; o; o >>= 1) cmax = fmaxf(cmax, __shfl_xor_sync(0xffffffffu, cmax, o));

            float s2 = 0.f;
            for (int k = lane; k < L_; k += 32) {
                float f = __expf(Srow[k] - cmax); Srow[k] = f; s2 += f;
            }
            #pragma unroll
            for (int o = 16; o; o >>= 1) s2 += __shfl_xor_sync(0xffffffffu, s2, o);
            if (lane == 0) rowInv[r] = 1.0f / s2;
        }
    }
    __syncthreads();

    // ---- phase 3: O = softmax2(P) @ V  (normalization in epilogue) ----
    {
        const int tx = tid & 15, ty = tid >> 4;   // (16,16): 2q x 4d micro
        float acc[2][4] = {};
        for (int k0 = 0; k0 < L_; k0 += 128) {
            #pragma unroll
            for (int l = 0; l < 8; l++) {
                int idx = tid + l * 256;          // V tile [128][68]
                int r = idx >> 4, c = (idx & 15) << 2;
                *(float4*)(KT + r * 68 + c) = *(const float4*)(Vb + (size_t)(k0 + r) * D_ + c);
            }
            __syncthreads();

            #pragma unroll 8
            for (int k = 0; k < 128; k++) {
                float s0 = S[(ty*2 + 0) * S_STRIDE + k0 + k];
                float s1 = S[(ty*2 + 1) * S_STRIDE + k0 + k];
                float4 v4 = *(float4*)(KT + k * 68 + tx * 4);
                acc[0][0] += s0 * v4.x; acc[0][1] += s0 * v4.y;
                acc[0][2] += s0 * v4.z; acc[0][3] += s0 * v4.w;
                acc[1][0] += s1 * v4.x; acc[1][1] += s1 * v4.y;
                acc[1][2] += s1 * v4.z; acc[1][3] += s1 * v4.w;
            }
            __syncthreads();
        }
        #pragma unroll
        for (int i = 0; i < 2; i++) {
            int r = ty * 2 + i;
            float sc = rowInv[r];
            float4 o = make_float4(acc[i][0]*sc, acc[i][1]*sc, acc[i][2]*sc, acc[i][3]*sc);
            *(float4*)(AV + ((size_t)(b * L_ + q0 + r)) * D_ + h * DK_ + tx * 4) = o;
        }
    }
}

// =================================================================
// launcher
// =================================================================
extern "C" void kernel_launch(void* const* d_in, const int* in_sizes, int n_in,
                              void* d_out, int out_size)
{
    const float* query   = (const float*)d_in[0];
    const float* key     = (const float*)d_in[1];
    const float* value   = (const float*)d_in[2];
    const float* wq_w    = (const float*)d_in[3];
    const float* wq_b    = (const float*)d_in[4];
    const float* wk_w    = (const float*)d_in[5];
    const float* wk_b    = (const float*)d_in[6];
    const float* wv_w    = (const float*)d_in[7];
    const float* wv_b    = (const float*)d_in[8];
    const float* dense_w = (const float*)d_in[9];
    const float* dense_b = (const float*)d_in[10];
    const float* gate_w  = (const float*)d_in[11];
    const float* gate_b  = (const float*)d_in[12];
    const float* mp_wq_w = (const float*)d_in[13];
    const float* mp_wq_b = (const float*)d_in[14];
    const float* mp_wk_w = (const float*)d_in[15];
    const float* mp_wk_b = (const float*)d_in[16];

    float* out  = (float*)d_out;                    // (B, L, D)
    float* mout = out + (size_t)B_ * L_ * D_;       // (B, L, L)

    float *Qd, *Kd, *Vd, *QPd, *KPd, *AVd, *gd;
    cudaGetSymbolAddress((void**)&Qd,  g_Q);
    cudaGetSymbolAddress((void**)&Kd,  g_K);
    cudaGetSymbolAddress((void**)&Vd,  g_V);
    cudaGetSymbolAddress((void**)&QPd, g_QP);
    cudaGetSymbolAddress((void**)&KPd, g_KP);
    cudaGetSymbolAddress((void**)&AVd, g_AV);
    cudaGetSymbolAddress((void**)&gd,  g_g);

    const int M = B_ * L_;                          // 4096
    dim3 gg(D_ / 64, M / 64);                       // (8, 64)

    sgemm_bias_kernel<<<gg, 256>>>(query, wq_w,    wq_b,    Qd,  M, D_, D_);
    sgemm_bias_kernel<<<gg, 256>>>(key,   wk_w,    wk_b,    Kd,  M, D_, D_);
    sgemm_bias_kernel<<<gg, 256>>>(value, wv_w,    wv_b,    Vd,  M, D_, D_);
    sgemm_bias_kernel<<<gg, 256>>>(query, mp_wq_w, mp_wq_b, QPd, M, D_, D_);
    sgemm_bias_kernel<<<gg, 256>>>(key,   mp_wk_w, mp_wk_b, KPd, M, D_, D_);

    gate_kernel<<<M / 8, 256>>>(query, gate_w, gate_b, gd);

    m_kernel<<<dim3(L_ / 64, L_ / 64, B_), 256>>>(QPd, KPd, mout);

    cudaFuncSetAttribute(attn_kernel,
                         cudaFuncAttributeMaxDynamicSharedMemorySize,
                         ATTN_SMEM_BYTES);
    attn_kernel<<<dim3(L_ / 32, H_, B_), 256, ATTN_SMEM_BYTES>>>(
        Qd, Kd, Vd, mout, gd, AVd);

    sgemm_bias_kernel<<<gg, 256>>>(AVd, dense_w, dense_b, out, M, D_, D_);
}

// round 7
// speedup vs baseline: 1.1847x; 1.1847x over previous
#include <cuda_runtime.h>

#define B_  4
#define L_  1024
#define D_  512
#define H_  8
#define DK_ 64

// ---------------- scratch (no allocations allowed) ----------------
__device__ float g_Q [B_*L_*D_];
__device__ float g_K [B_*L_*D_];
__device__ float g_V [B_*L_*D_];
__device__ float g_QP[B_*L_*D_];
__device__ float g_KP[B_*L_*D_];
__device__ float g_AV[B_*L_*D_];
__device__ float g_g [B_*L_];

// =================================================================
// Core NN SGEMM tile: C[M,N] = A[M,512] @ W[512,N] + bias
// 128x128 tile, BK=16, 256 threads, 8x8 micro-tile.
// M indexed by blockIdx.y, N by blockIdx.x. N=K=512 fixed.
// =================================================================
__device__ __forceinline__ void gemm_nn_core(
    const float* __restrict__ A, const float* __restrict__ W,
    const float* __restrict__ bias, float* __restrict__ C,
    float As[16][132], float Ws[16][132])
{
    const int tid = threadIdx.x;
    const int tx = tid & 15;          // n micro-group
    const int ty = tid >> 4;          // m micro-group
    const int m0 = blockIdx.y * 128, n0 = blockIdx.x * 128;

    float acc[8][8] = {};

    for (int k0 = 0; k0 < 512; k0 += 16) {
        // A tile 128x16 -> As[k][m] (transposed). Thread owns row (tid&127),
        // loads 2 float4 chunks along k. STS: same c per warp, consecutive r
        // -> conflict-free.
        #pragma unroll
        for (int l = 0; l < 2; l++) {
            int idx = tid + l * 256;
            int r = idx & 127;
            int c = (idx >> 7) * 4;
            float4 v = *(const float4*)(A + (size_t)(m0 + r) * 512 + k0 + c);
            As[c+0][r] = v.x; As[c+1][r] = v.y;
            As[c+2][r] = v.z; As[c+3][r] = v.w;
        }
        // W tile 16x128 -> Ws[k][n] direct float4 stores.
        #pragma unroll
        for (int l = 0; l < 2; l++) {
            int idx = tid + l * 256;
            int r = idx >> 5;               // k 0..15
            int c = (idx & 31) * 4;         // n 0..124
            *(float4*)&Ws[r][c] = *(const float4*)(W + (size_t)(k0 + r) * 512 + n0 + c);
        }
        __syncthreads();

        #pragma unroll
        for (int kk = 0; kk < 16; kk++) {
            float a_[8], b_[8];
            float4 t;
            t = *(float4*)&As[kk][ty * 4];      a_[0]=t.x; a_[1]=t.y; a_[2]=t.z; a_[3]=t.w;
            t = *(float4*)&As[kk][ty * 4 + 64]; a_[4]=t.x; a_[5]=t.y; a_[6]=t.z; a_[7]=t.w;
            t = *(float4*)&Ws[kk][tx * 4];      b_[0]=t.x; b_[1]=t.y; b_[2]=t.z; b_[3]=t.w;
            t = *(float4*)&Ws[kk][tx * 4 + 64]; b_[4]=t.x; b_[5]=t.y; b_[6]=t.z; b_[7]=t.w;
            #pragma unroll
            for (int i = 0; i < 8; i++)
                #pragma unroll
                for (int j = 0; j < 8; j++)
                    acc[i][j] += a_[i] * b_[j];
        }
        __syncthreads();
    }

    float4 bv0 = *(const float4*)(bias + n0 + tx * 4);
    float4 bv1 = *(const float4*)(bias + n0 + tx * 4 + 64);
    #pragma unroll
    for (int i = 0; i < 8; i++) {
        int row = m0 + ((i < 4) ? (ty * 4 + i) : (64 + ty * 4 + i - 4));
        float4 o0 = make_float4(acc[i][0] + bv0.x, acc[i][1] + bv0.y,
                                acc[i][2] + bv0.z, acc[i][3] + bv0.w);
        float4 o1 = make_float4(acc[i][4] + bv1.x, acc[i][5] + bv1.y,
                                acc[i][6] + bv1.z, acc[i][7] + bv1.w);
        *(float4*)(C + (size_t)row * 512 + n0 + tx * 4)      = o0;
        *(float4*)(C + (size_t)row * 512 + n0 + tx * 4 + 64) = o1;
    }
}

struct Proj5 {
    const float* A[5];
    const float* W[5];
    const float* bias[5];
    float*       C[5];
};

// 5 projection GEMMs batched by blockIdx.z
__global__ __launch_bounds__(256, 2) void proj5_kernel(Proj5 p)
{
    __shared__ float As[16][132];
    __shared__ float Ws[16][132];
    const int z = blockIdx.z;
    gemm_nn_core(p.A[z], p.W[z], p.bias[z], p.C[z], As, Ws);
}

// final dense GEMM
__global__ __launch_bounds__(256, 2) void dense_kernel(
    const float* __restrict__ A, const float* __restrict__ W,
    const float* __restrict__ bias, float* __restrict__ C)
{
    __shared__ float As[16][132];
    __shared__ float Ws[16][132];
    gemm_nn_core(A, W, bias, C, As, Ws);
}

// =================================================================
// m kernel: per batch  m = sigmoid( (QP @ KP^T) / sqrt(512) )
// NT GEMM 128x128, BK=16, 8x8 micro, fused sigmoid -> d_out m region
// =================================================================
__global__ __launch_bounds__(256, 2) void m_kernel(
    const float* __restrict__ QP, const float* __restrict__ KP,
    float* __restrict__ Mout)
{
    const int bz = blockIdx.z;
    const float* A  = QP + (size_t)bz * L_ * D_;
    const float* Bp = KP + (size_t)bz * L_ * D_;
    float* C = Mout + (size_t)bz * L_ * L_;

    __shared__ float As[16][132];
    __shared__ float Bs[16][132];
    const int tid = threadIdx.x;
    const int tx = tid & 15, ty = tid >> 4;
    const int m0 = blockIdx.y * 128, n0 = blockIdx.x * 128;

    float acc[8][8] = {};

    for (int k0 = 0; k0 < 512; k0 += 16) {
        #pragma unroll
        for (int l = 0; l < 2; l++) {
            int idx = tid + l * 256;
            int r = idx & 127;
            int c = (idx >> 7) * 4;
            float4 v = *(const float4*)(A + (size_t)(m0 + r) * 512 + k0 + c);
            As[c+0][r] = v.x; As[c+1][r] = v.y;
            As[c+2][r] = v.z; As[c+3][r] = v.w;
            float4 w = *(const float4*)(Bp + (size_t)(n0 + r) * 512 + k0 + c);
            Bs[c+0][r] = w.x; Bs[c+1][r] = w.y;
            Bs[c+2][r] = w.z; Bs[c+3][r] = w.w;
        }
        __syncthreads();

        #pragma unroll
        for (int kk = 0; kk < 16; kk++) {
            float a_[8], b_[8];
            float4 t;
            t = *(float4*)&As[kk][ty * 4];      a_[0]=t.x; a_[1]=t.y; a_[2]=t.z; a_[3]=t.w;
            t = *(float4*)&As[kk][ty * 4 + 64]; a_[4]=t.x; a_[5]=t.y; a_[6]=t.z; a_[7]=t.w;
            t = *(float4*)&Bs[kk][tx * 4];      b_[0]=t.x; b_[1]=t.y; b_[2]=t.z; b_[3]=t.w;
            t = *(float4*)&Bs[kk][tx * 4 + 64]; b_[4]=t.x; b_[5]=t.y; b_[6]=t.z; b_[7]=t.w;
            #pragma unroll
            for (int i = 0; i < 8; i++)
                #pragma unroll
                for (int j = 0; j < 8; j++)
                    acc[i][j] += a_[i] * b_[j];
        }
        __syncthreads();
    }

    const float sc = 0.04419417382415922f;   // 1/sqrt(512)
    #pragma unroll
    for (int i = 0; i < 8; i++) {
        int row = m0 + ((i < 4) ? (ty * 4 + i) : (64 + ty * 4 + i - 4));
        float4 o0, o1;
        o0.x = 1.0f / (1.0f + __expf(-acc[i][0] * sc));
        o0.y = 1.0f / (1.0f + __expf(-acc[i][1] * sc));
        o0.z = 1.0f / (1.0f + __expf(-acc[i][2] * sc));
        o0.w = 1.0f / (1.0f + __expf(-acc[i][3] * sc));
        o1.x = 1.0f / (1.0f + __expf(-acc[i][4] * sc));
        o1.y = 1.0f / (1.0f + __expf(-acc[i][5] * sc));
        o1.z = 1.0f / (1.0f + __expf(-acc[i][6] * sc));
        o1.w = 1.0f / (1.0f + __expf(-acc[i][7] * sc));
        *(float4*)(C + (size_t)row * L_ + n0 + tx * 4)      = o0;
        *(float4*)(C + (size_t)row * L_ + n0 + tx * 4 + 64) = o1;
    }
}

// =================================================================
// gate kernel: g = sigmoid(query @ gate_w + gate_b), one warp per row
// =================================================================
__global__ __launch_bounds__(256) void gate_kernel(
    const float* __restrict__ query, const float* __restrict__ gw,
    const float* __restrict__ gb, float* __restrict__ g)
{
    const int row  = blockIdx.x * 8 + (threadIdx.x >> 5);
    const int lane = threadIdx.x & 31;
    const float* q = query + (size_t)row * D_;
    float s = 0.f;
    #pragma unroll
    for (int k = lane; k < D_; k += 32) s += q[k] * gw[k];
    #pragma unroll
    for (int o = 16; o; o >>= 1) s += __shfl_xor_sync(0xffffffffu, s, o);
    if (lane == 0) g[row] = 1.0f / (1.0f + __expf(-(s + gb[0])));
}

// =================================================================
// Fused attention kernel: one block = (b, h, 32 query rows).
// S: full 32x1024 scores in smem; two softmaxes + calibration fused.
// Phase1: 4q x 8k micro (split-half k frag). Phase3: k-unroll 4 w/ float4 S.
// =================================================================
#define S_STRIDE 1032
#define QT_OFF   (32 * S_STRIDE)              // 33024
#define KT_OFF   (QT_OFF + 64 * 36)           // 35328
#define SMEM_FLOATS (KT_OFF + 64 * 260)       // 51968
#define ATTN_SMEM_BYTES (SMEM_FLOATS * 4)     // 207872

__global__ __launch_bounds__(256) void attn_kernel(
    const float* __restrict__ Q, const float* __restrict__ Kg,
    const float* __restrict__ Vg, const float* __restrict__ Mg,
    const float* __restrict__ gate, float* __restrict__ AV)
{
    extern __shared__ float sm[];
    float* S  = sm;              // [32][1032]
    float* QT = sm + QT_OFF;     // [64][36]   Q^T [d][q]
    float* KT = sm + KT_OFF;     // [64][260]  K^T [d][k256]  (also V tile [128][68])
    __shared__ float rowInv[32];

    const int tid = threadIdx.x;
    const int b = blockIdx.z, h = blockIdx.y, q0 = blockIdx.x * 32;

    const float* Qb = Q  + ((size_t)(b * L_ + q0)) * D_ + h * DK_;
    const float* Kb = Kg + (size_t)b * L_ * D_ + h * DK_;
    const float* Vb = Vg + (size_t)b * L_ * D_ + h * DK_;
    const float* Mb = Mg + (size_t)b * L_ * L_ + (size_t)q0 * L_;

    // ---- load Q tile transposed: QT[d][q], conflict-free STS ----
    #pragma unroll
    for (int l = 0; l < 2; l++) {
        int idx = tid + l * 256;              // 512 float4 : 32 rows x 16 chunks
        int r = idx & 31;
        int c = (idx >> 5) * 4;
        float4 v = *(const float4*)(Qb + (size_t)r * D_ + c);
        QT[(c+0)*36 + r] = v.x; QT[(c+1)*36 + r] = v.y;
        QT[(c+2)*36 + r] = v.z; QT[(c+3)*36 + r] = v.w;
    }

    // ---- phase 1: S = (Q K^T) * 1/sqrt(64), k-chunks of 256 ----
    {
        const int tx = tid & 31;              // k micro-group (32)
        const int ty = tid >> 5;              // q micro-group (8)
        for (int k0 = 0; k0 < L_; k0 += 256) {
            // K tile 256x64 -> KT[d][k]; thread owns k-row (k0+tid)
            #pragma unroll
            for (int l = 0; l < 16; l++) {
                int idx = tid + l * 256;
                int r = idx & 255;
                int c = (idx >> 8) * 4;
                float4 v = *(const float4*)(Kb + (size_t)(k0 + r) * D_ + c);
                KT[(c+0)*260 + r] = v.x; KT[(c+1)*260 + r] = v.y;
                KT[(c+2)*260 + r] = v.z; KT[(c+3)*260 + r] = v.w;
            }
            __syncthreads();

            float acc[4][8] = {};
            #pragma unroll 8
            for (int d = 0; d < 64; d++) {
                float4 a4 = *(float4*)(QT + d * 36 + ty * 4);
                float4 b0 = *(float4*)(KT + d * 260 + tx * 4);
                float4 b1 = *(float4*)(KT + d * 260 + 128 + tx * 4);
                float a_[4] = {a4.x, a4.y, a4.z, a4.w};
                float b_[8] = {b0.x, b0.y, b0.z, b0.w, b1.x, b1.y, b1.z, b1.w};
                #pragma unroll
                for (int i = 0; i < 4; i++)
                    #pragma unroll
                    for (int j = 0; j < 8; j++)
                        acc[i][j] += a_[i] * b_[j];
            }
            #pragma unroll
            for (int i = 0; i < 4; i++) {
                float* Srow = S + (ty * 4 + i) * S_STRIDE + k0;
                float4 o0 = make_float4(acc[i][0]*0.125f, acc[i][1]*0.125f,
                                        acc[i][2]*0.125f, acc[i][3]*0.125f);
                float4 o1 = make_float4(acc[i][4]*0.125f, acc[i][5]*0.125f,
                                        acc[i][6]*0.125f, acc[i][7]*0.125f);
                *(float4*)(Srow + tx * 4)       = o0;
                *(float4*)(Srow + 128 + tx * 4) = o1;
            }
            __syncthreads();
        }
    }

    // ---- phase 2: softmax -> calibrate with m,g -> second softmax ----
    {
        const int warp = tid >> 5, lane = tid & 31;
        #pragma unroll
        for (int rr = 0; rr < 4; rr++) {
            const int r = warp * 4 + rr;
            float4* Srow4 = (float4*)(S + r * S_STRIDE);

            float mx = -1e30f;
            for (int i = lane; i < 256; i += 32) {
                float4 v = Srow4[i];
                mx = fmaxf(mx, fmaxf(fmaxf(v.x, v.y), fmaxf(v.z, v.w)));
            }
            #pragma unroll
            for (int o = 16; o; o >>= 1) mx = fmaxf(mx, __shfl_xor_sync(0xffffffffu, mx, o));

            float sum = 0.f;
            for (int i = lane; i < 256; i += 32) {
                float4 v = Srow4[i];
                v.x = __expf(v.x - mx); v.y = __expf(v.y - mx);
                v.z = __expf(v.z - mx); v.w = __expf(v.w - mx);
                Srow4[i] = v;
                sum += v.x + v.y + v.z + v.w;
            }
            #pragma unroll
            for (int o = 16; o; o >>= 1) sum += __shfl_xor_sync(0xffffffffu, sum, o);
            const float inv = 1.0f / sum;

            const float gq = gate[b * L_ + q0 + r];
            const float gq1 = 1.0f - gq;
            const float4* mrow4 = (const float4*)(Mb + (size_t)r * L_);
            float cmax = -1e30f;
            for (int i = lane; i < 256; i += 32) {
                float4 v = Srow4[i];
                float4 mm = mrow4[i];
                v.x *= inv * (gq + gq1 * __expf(1.0f - mm.x));
                v.y *= inv * (gq + gq1 * __expf(1.0f - mm.y));
                v.z *= inv * (gq + gq1 * __expf(1.0f - mm.z));
                v.w *= inv * (gq + gq1 * __expf(1.0f - mm.w));
                Srow4[i] = v;
                cmax = fmaxf(cmax, fmaxf(fmaxf(v.x, v.y), fmaxf(v.z, v.w)));
            }
            #pragma unroll
            for (int o = 16; o; o >>= 1) cmax = fmaxf(cmax, __shfl_xor_sync(0xffffffffu, cmax, o));

            float s2 = 0.f;
            for (int i = lane; i < 256; i += 32) {
                float4 v = Srow4[i];
                v.x = __expf(v.x - cmax); v.y = __expf(v.y - cmax);
                v.z = __expf(v.z - cmax); v.w = __expf(v.w - cmax);
                Srow4[i] = v;
                s2 += v.x + v.y + v.z + v.w;
            }
            #pragma unroll
            for (int o = 16; o; o >>= 1) s2 += __shfl_xor_sync(0xffffffffu, s2, o);
            if (lane == 0) rowInv[r] = 1.0f / s2;
        }
    }
    __syncthreads();

    // ---- phase 3: O = softmax2(P) @ V, k-unroll 4 with float4 S loads ----
    {
        const int tx = tid & 15, ty = tid >> 4;   // 2q x 4d micro
        float acc[2][4] = {};
        const float* S0 = S + (ty * 2 + 0) * S_STRIDE;
        const float* S1 = S + (ty * 2 + 1) * S_STRIDE;
        for (int k0 = 0; k0 < L_; k0 += 128) {
            #pragma unroll
            for (int l = 0; l < 8; l++) {
                int idx = tid + l * 256;          // V tile [128][68]
                int r = idx >> 4, c = (idx & 15) << 2;
                *(float4*)(KT + r * 68 + c) = *(const float4*)(Vb + (size_t)(k0 + r) * D_ + c);
            }
            __syncthreads();

            #pragma unroll 4
            for (int k4 = 0; k4 < 32; k4++) {
                float4 s0 = *(const float4*)(S0 + k0 + k4 * 4);
                float4 s1 = *(const float4*)(S1 + k0 + k4 * 4);
                float sa0[4] = {s0.x, s0.y, s0.z, s0.w};
                float sa1[4] = {s1.x, s1.y, s1.z, s1.w};
                #pragma unroll
                for (int j = 0; j < 4; j++) {
                    float4 v4 = *(float4*)(KT + (k4 * 4 + j) * 68 + tx * 4);
                    acc[0][0] += sa0[j] * v4.x; acc[0][1] += sa0[j] * v4.y;
                    acc[0][2] += sa0[j] * v4.z; acc[0][3] += sa0[j] * v4.w;
                    acc[1][0] += sa1[j] * v4.x; acc[1][1] += sa1[j] * v4.y;
                    acc[1][2] += sa1[j] * v4.z; acc[1][3] += sa1[j] * v4.w;
                }
            }
            __syncthreads();
        }
        #pragma unroll
        for (int i = 0; i < 2; i++) {
            int r = ty * 2 + i;
            float sc = rowInv[r];
            float4 o = make_float4(acc[i][0]*sc, acc[i][1]*sc, acc[i][2]*sc, acc[i][3]*sc);
            *(float4*)(AV + ((size_t)(b * L_ + q0 + r)) * D_ + h * DK_ + tx * 4) = o;
        }
    }
}

// =================================================================
// launcher
// =================================================================
extern "C" void kernel_launch(void* const* d_in, const int* in_sizes, int n_in,
                              void* d_out, int out_size)
{
    const float* query   = (const float*)d_in[0];
    const float* key     = (const float*)d_in[1];
    const float* value   = (const float*)d_in[2];
    const float* wq_w    = (const float*)d_in[3];
    const float* wq_b    = (const float*)d_in[4];
    const float* wk_w    = (const float*)d_in[5];
    const float* wk_b    = (const float*)d_in[6];
    const float* wv_w    = (const float*)d_in[7];
    const float* wv_b    = (const float*)d_in[8];
    const float* dense_w = (const float*)d_in[9];
    const float* dense_b = (const float*)d_in[10];
    const float* gate_w  = (const float*)d_in[11];
    const float* gate_b  = (const float*)d_in[12];
    const float* mp_wq_w = (const float*)d_in[13];
    const float* mp_wq_b = (const float*)d_in[14];
    const float* mp_wk_w = (const float*)d_in[15];
    const float* mp_wk_b = (const float*)d_in[16];

    float* out  = (float*)d_out;                    // (B, L, D)
    float* mout = out + (size_t)B_ * L_ * D_;       // (B, L, L)

    float *Qd, *Kd, *Vd, *QPd, *KPd, *AVd, *gd;
    cudaGetSymbolAddress((void**)&Qd,  g_Q);
    cudaGetSymbolAddress((void**)&Kd,  g_K);
    cudaGetSymbolAddress((void**)&Vd,  g_V);
    cudaGetSymbolAddress((void**)&QPd, g_QP);
    cudaGetSymbolAddress((void**)&KPd, g_KP);
    cudaGetSymbolAddress((void**)&AVd, g_AV);
    cudaGetSymbolAddress((void**)&gd,  g_g);

    // 5 projection GEMMs in one launch (z picks operands)
    Proj5 p;
    p.A[0] = query; p.W[0] = wq_w;    p.bias[0] = wq_b;    p.C[0] = Qd;
    p.A[1] = key;   p.W[1] = wk_w;    p.bias[1] = wk_b;    p.C[1] = Kd;
    p.A[2] = value; p.W[2] = wv_w;    p.bias[2] = wv_b;    p.C[2] = Vd;
    p.A[3] = query; p.W[3] = mp_wq_w; p.bias[3] = mp_wq_b; p.C[3] = QPd;
    p.A[4] = key;   p.W[4] = mp_wk_w; p.bias[4] = mp_wk_b; p.C[4] = KPd;

    proj5_kernel<<<dim3(D_ / 128, (B_ * L_) / 128, 5), 256>>>(p);

    gate_kernel<<<(B_ * L_) / 8, 256>>>(query, gate_w, gate_b, gd);

    m_kernel<<<dim3(L_ / 128, L_ / 128, B_), 256>>>(QPd, KPd, mout);

    cudaFuncSetAttribute(attn_kernel,
                         cudaFuncAttributeMaxDynamicSharedMemorySize,
                         ATTN_SMEM_BYTES);
    attn_kernel<<<dim3(L_ / 32, H_, B_), 256, ATTN_SMEM_BYTES>>>(
        Qd, Kd, Vd, mout, gd, AVd);

    dense_kernel<<<dim3(D_ / 128, (B_ * L_) / 128), 256>>>(AVd, dense_w, dense_b, out);
}